// round 15
// baseline (speedup 1.0000x reference)
#include <cuda_runtime.h>
#include <cuda_fp16.h>
#include <math.h>
#include <stdint.h>

// ---------------------------------------------------------------------------
// SharedSpecialistMoEFFN — GB300 (sm_103, legacy tensor path), Round 14
// Crossbar-relief GEMM: BM=128 BN=256 BK=64, warp tile 64x64 (8 warps 2x4),
// occ 1, 3 stages, af+bf double-buffered across kk (fixes R10's serialization).
// Schedule/router identical to R13 (best: 1128.5us).
// ---------------------------------------------------------------------------

#define D_MODEL 1024
#define D_FF    4096
#define N_EXP   8
#define T_TOK   8192
#define MAX_BLOCKS 136
#define MAX_SLOTS  (MAX_BLOCKS * 128)

#define STAGES      3
#define A_ROW       144                 // 128B data + 16B pad
#define A_STAGE_SZ  (128 * A_ROW)       // 18432
#define B_STAGE_SZ  (64 * 512)          // 32768 (BN=256 fp16)
#define STAGE_BYTES (A_STAGE_SZ + B_STAGE_SZ)   // 51200
#define SMEM_TOTAL  (STAGES * STAGE_BYTES)      // 153600

// ---------------- scratch (device globals; zero runtime allocation) --------
__device__ __half g_xh[(size_t)T_TOK * D_MODEL];
__device__ __half g_w1h[(size_t)D_MODEL * D_FF];
__device__ __half g_w2h[(size_t)D_FF * D_MODEL];
__device__ __half g_ew1h[(size_t)N_EXP * D_MODEL * D_FF];
__device__ __half g_ew2h[(size_t)N_EXP * D_FF * D_MODEL];
__device__ __half g_Hsh[(size_t)T_TOK * D_FF];
__device__ __half g_Heh[(size_t)MAX_SLOTS * D_FF];
__device__ float  g_Ye[(size_t)MAX_SLOTS * D_MODEL];
__device__ int    g_perm[MAX_SLOTS];
__device__ int    g_topidx[T_TOK * 2];
__device__ float  g_topw[T_TOK * 2];
__device__ int    g_slot[T_TOK * 2];
__device__ int    g_counts[N_EXP];
__device__ int    g_cursor[N_EXP];
__device__ int    g_offsets[N_EXP];
__device__ int    g_blk_expert[MAX_BLOCKS];
__device__ int    g_nblocks;

// ---------------- helpers ---------------------------------------------------
__device__ __forceinline__ float gelu_exact(float v) {
    return 0.5f * v * (1.0f + erff(v * 0.70710678118654752f));
}
__device__ __forceinline__ uint32_t s2u(const void* p) {
    uint32_t a;
    asm("{ .reg .u64 t; cvta.to.shared.u64 t, %1; cvt.u32.u64 %0, t; }" : "=r"(a) : "l"(p));
    return a;
}
__device__ __forceinline__ void cp16(uint32_t dst, const void* src) {
    asm volatile("cp.async.cg.shared.global [%0], [%1], 16;" :: "r"(dst), "l"(src));
}
__device__ __forceinline__ void cp16s(uint32_t dst, const void* src, int sz) {
    asm volatile("cp.async.cg.shared.global [%0], [%1], 16, %2;"
                 :: "r"(dst), "l"(src), "r"(sz));
}
__device__ __forceinline__ void ldm_x4(uint32_t* r, uint32_t addr) {
    asm volatile("ldmatrix.sync.aligned.m8n8.x4.shared.b16 {%0,%1,%2,%3}, [%4];"
                 : "=r"(r[0]), "=r"(r[1]), "=r"(r[2]), "=r"(r[3]) : "r"(addr));
}
__device__ __forceinline__ void ldm_x4t(uint32_t* r, uint32_t addr) {
    asm volatile("ldmatrix.sync.aligned.m8n8.x4.trans.shared.b16 {%0,%1,%2,%3}, [%4];"
                 : "=r"(r[0]), "=r"(r[1]), "=r"(r[2]), "=r"(r[3]) : "r"(addr));
}
__device__ __forceinline__ void mma_f16(float c[4], const uint32_t a[4],
                                        uint32_t b0, uint32_t b1) {
    asm volatile(
        "mma.sync.aligned.m16n8k16.row.col.f32.f16.f16.f32 "
        "{%0,%1,%2,%3}, {%4,%5,%6,%7}, {%8,%9}, {%0,%1,%2,%3};\n"
        : "+f"(c[0]), "+f"(c[1]), "+f"(c[2]), "+f"(c[3])
        : "r"(a[0]), "r"(a[1]), "r"(a[2]), "r"(a[3]), "r"(b0), "r"(b1));
}

// ---------------- prep: fp32 -> fp16 ----------------------------------------
__global__ void f2h_kernel(const float* __restrict__ in, __half2* __restrict__ out) {
    size_t i = (size_t)blockIdx.x * blockDim.x + threadIdx.x;
    float4 v = ((const float4*)in)[i];
    out[i * 2 + 0] = __floats2half2_rn(v.x, v.y);
    out[i * 2 + 1] = __floats2half2_rn(v.z, v.w);
}

// ---------------- routing helpers -------------------------------------------
__global__ void init_kernel() {
    int i = threadIdx.x;
    if (i < N_EXP) { g_counts[i] = 0; g_cursor[i] = 0; }
}

// Router v2 (measured best): 4 tokens per warp.
__global__ void router_kernel(const float* __restrict__ x,
                              const float* __restrict__ rw,
                              const float* __restrict__ rb) {
    int warp = threadIdx.x >> 5, lane = threadIdx.x & 31;
    int t0 = (blockIdx.x * 8 + warp) * 4;
    const float* xr = x + (size_t)t0 * D_MODEL;
    float acc[4][8];
#pragma unroll
    for (int tt = 0; tt < 4; ++tt)
#pragma unroll
        for (int e = 0; e < 8; ++e) acc[tt][e] = 0.f;
    for (int i = lane; i < D_MODEL; i += 32) {
        const float4* r = (const float4*)(rw + (size_t)i * 8);
        float4 rA = r[0], rB = r[1];
#pragma unroll
        for (int tt = 0; tt < 4; ++tt) {
            float xv = xr[(size_t)tt * D_MODEL + i];
            acc[tt][0] += xv * rA.x; acc[tt][1] += xv * rA.y;
            acc[tt][2] += xv * rA.z; acc[tt][3] += xv * rA.w;
            acc[tt][4] += xv * rB.x; acc[tt][5] += xv * rB.y;
            acc[tt][6] += xv * rB.z; acc[tt][7] += xv * rB.w;
        }
    }
#pragma unroll
    for (int off = 16; off; off >>= 1)
#pragma unroll
        for (int tt = 0; tt < 4; ++tt)
#pragma unroll
            for (int e = 0; e < 8; ++e)
                acc[tt][e] += __shfl_xor_sync(0xffffffffu, acc[tt][e], off);
    if (lane == 0) {
#pragma unroll
        for (int tt = 0; tt < 4; ++tt) {
            int t = t0 + tt;
            float l[8], m = -1e30f;
#pragma unroll
            for (int e = 0; e < 8; ++e) { l[e] = acc[tt][e] + rb[e]; m = fmaxf(m, l[e]); }
            float p[8], Z = 0.f;
#pragma unroll
            for (int e = 0; e < 8; ++e) { p[e] = expf(l[e] - m); Z += p[e]; }
#pragma unroll
            for (int e = 0; e < 8; ++e) p[e] /= Z;
            int i0 = 0;
#pragma unroll
            for (int e = 1; e < 8; ++e) if (p[e] > p[i0]) i0 = e;
            int i1 = -1;
            for (int e = 0; e < 8; ++e) if (e != i0 && (i1 < 0 || p[e] > p[i1])) i1 = e;
            float s = p[i0] + p[i1] + 1e-9f;
            g_topidx[t * 2 + 0] = i0;
            g_topidx[t * 2 + 1] = i1;
            g_topw[t * 2 + 0] = p[i0] / s;
            g_topw[t * 2 + 1] = p[i1] / s;
            atomicAdd(&g_counts[i0], 1);
            atomicAdd(&g_counts[i1], 1);
        }
    }
}

// scan + pad-fill
__global__ void scan_kernel() {
    __shared__ int offs[N_EXP], cnts[N_EXP], ends[N_EXP];
    if (threadIdx.x == 0) {
        int tb = 0;
        for (int e = 0; e < N_EXP; ++e) {
            int cnt = g_counts[e];
            offs[e] = tb * 128;
            cnts[e] = cnt;
            int nb = (cnt + 127) >> 7;
            for (int b = 0; b < nb; ++b) g_blk_expert[tb + b] = e;
            tb += nb;
            ends[e] = tb * 128;
        }
        g_nblocks = tb;
        for (int e = 0; e < N_EXP; ++e) g_offsets[e] = offs[e];
    }
    __syncthreads();
#pragma unroll
    for (int e = 0; e < N_EXP; ++e) {
        int start = offs[e] + cnts[e], end = ends[e];
        for (int i = start + threadIdx.x; i < end; i += blockDim.x)
            g_perm[i] = -1;
    }
}

__global__ void gather_kernel() {
    int t = blockIdx.x * blockDim.x + threadIdx.x;
    if (t >= T_TOK) return;
#pragma unroll
    for (int k = 0; k < 2; ++k) {
        int e = g_topidx[t * 2 + k];
        int pos = atomicAdd(&g_cursor[e], 1);
        int slot = g_offsets[e] + pos;
        g_perm[slot] = t;
        g_slot[t * 2 + k] = slot;
    }
}

__global__ void combine_kernel(float* __restrict__ out, const float* __restrict__ Ye) {
    int t = blockIdx.x;
    int col = threadIdx.x * 4;
    int s0 = g_slot[t * 2 + 0], s1 = g_slot[t * 2 + 1];
    float w0 = g_topw[t * 2 + 0], w1 = g_topw[t * 2 + 1];
    float4 o = *(const float4*)(out + (size_t)t * D_MODEL + col);
    float4 y0 = *(const float4*)(Ye + (size_t)s0 * D_MODEL + col);
    float4 y1 = *(const float4*)(Ye + (size_t)s1 * D_MODEL + col);
    o.x += w0 * y0.x + w1 * y1.x;
    o.y += w0 * y0.y + w1 * y1.y;
    o.z += w0 * y0.z + w1 * y1.z;
    o.w += w0 * y0.w + w1 * y1.w;
    *(float4*)(out + (size_t)t * D_MODEL + col) = o;
}

// ---------------- fp16 GEMM: BM=128 BN=256 BK=64, 64x64 warp tiles, occ 1 ---
// af+bf double-buffered across the 4 k16 slices of each BK=64 stage.
template <bool GELU, bool PERM, bool EXPERT, bool HALF_OUT>
__global__ __launch_bounds__(256, 1)
void gemm_h(const __half* __restrict__ A, const __half* __restrict__ Bw,
            const float* __restrict__ bias, void* __restrict__ Cv,
            int Ntot, int K, long wstride, long bstride) {
    int bm = blockIdx.x, bn = blockIdx.y;
    if (EXPERT) {
        if (bm >= g_nblocks) return;
        int e = g_blk_expert[bm];
        Bw += (long)e * wstride;
        bias += (long)e * bstride;
    }
    extern __shared__ char smem[];
    const uint32_t sb = s2u(smem);
    const int tid = threadIdx.x, lane = tid & 31, w = tid >> 5;
    const int wm = w & 1, wn = w >> 1;   // 2 (m) x 4 (n) warps, 64x64 tiles

    // --- A loader: 4 chunks/thread (128 rows x 8 f16x8-chunks) --------------
    const __half* a_src[4]; uint32_t a_dst[4]; int a_sz[4];
#pragma unroll
    for (int i = 0; i < 4; ++i) {
        int r = (tid >> 3) + 32 * i, f = tid & 7;
        a_dst[i] = (uint32_t)(r * A_ROW + f * 16);
        long row = PERM ? (long)g_perm[bm * 128 + r] : (long)bm * 128 + r;
        if (row >= 0) { a_src[i] = A + row * (long)K + f * 8; a_sz[i] = 16; }
        else          { a_src[i] = A;                          a_sz[i] = 0;  }
    }
    // --- B loader: 8 chunks/thread (64 k-rows x 512B) -----------------------
    const int bj = tid & 31, bk0 = tid >> 5;
    const __half* b_src0 = Bw + (long)bk0 * Ntot + (long)bn * 256 + bj * 8;
    const uint32_t b_dst0 =
        (uint32_t)(A_STAGE_SZ + bk0 * 512 + ((bj ^ (bk0 & 7)) * 16));
    const long bKstep = (long)64 * Ntot;

    float acc[4][8][4];
#pragma unroll
    for (int i = 0; i < 4; ++i)
#pragma unroll
        for (int j = 0; j < 8; ++j)
#pragma unroll
            for (int q = 0; q < 4; ++q) acc[i][j][q] = 0.f;

    const int KT = K >> 6;

    // prologue: stages 0..1
#pragma unroll
    for (int p = 0; p < STAGES - 1; ++p) {
        uint32_t st = sb + p * STAGE_BYTES;
#pragma unroll
        for (int i = 0; i < 4; ++i) cp16s(st + a_dst[i], a_src[i] + (long)p * 64, a_sz[i]);
#pragma unroll
        for (int i = 0; i < 8; ++i)
            cp16(st + b_dst0 + i * 8 * 512, b_src0 + (long)p * bKstep + (long)i * 8 * Ntot);
        asm volatile("cp.async.commit_group;" ::: "memory");
    }

    // ldmatrix bases
    const uint32_t aBase = (uint32_t)((wm * 64 + (lane & 15)) * A_ROW + (lane >> 4) * 16);
    const uint32_t bRow = (uint32_t)(A_STAGE_SZ + (((lane >> 3) & 1) * 8 + (lane & 7)) * 512);
    uint32_t bCh[4];
#pragma unroll
    for (int p = 0; p < 4; ++p)
        bCh[p] = (uint32_t)(((wn * 8 + 2 * p + (lane >> 4)) ^ (lane & 7)) * 16);

    uint32_t rd = sb;
    uint32_t wr = sb + (STAGES - 1) * STAGE_BYTES;
    const uint32_t hiS = sb + STAGES * STAGE_BYTES;

    for (int kt = 0; kt < KT; ++kt) {
        asm volatile("cp.async.wait_group %0;" :: "n"(STAGES - 2) : "memory");
        __syncthreads();

        uint32_t bf[2][16], af[2][4][4];
        // preload kk = 0
#pragma unroll
        for (int p = 0; p < 4; ++p)
            ldm_x4t(&bf[0][p * 4], rd + bRow + bCh[p]);
#pragma unroll
        for (int mi = 0; mi < 4; ++mi)
            ldm_x4(af[0][mi], rd + aBase + mi * 16 * A_ROW);
#pragma unroll
        for (int kk = 0; kk < 4; ++kk) {
            const int cur = kk & 1;
            if (kk < 3) {   // prefetch kk+1 fragments under this kk's mma chain
#pragma unroll
                for (int p = 0; p < 4; ++p)
                    ldm_x4t(&bf[cur ^ 1][p * 4], rd + bRow + (kk + 1) * 8192 + bCh[p]);
#pragma unroll
                for (int mi = 0; mi < 4; ++mi)
                    ldm_x4(af[cur ^ 1][mi], rd + aBase + mi * 16 * A_ROW + (kk + 1) * 32);
            }
#pragma unroll
            for (int mi = 0; mi < 4; ++mi)
#pragma unroll
                for (int ni = 0; ni < 8; ++ni) {
                    const int p = ni >> 1, h = ni & 1;
                    mma_f16(acc[mi][ni], af[cur][mi],
                            bf[cur][p * 4 + h * 2], bf[cur][p * 4 + h * 2 + 1]);
                }
        }

        if (kt + STAGES - 1 < KT) {
            const long nx = kt + STAGES - 1;
#pragma unroll
            for (int i = 0; i < 4; ++i)
                cp16s(wr + a_dst[i], a_src[i] + nx * 64, a_sz[i]);
#pragma unroll
            for (int i = 0; i < 8; ++i)
                cp16(wr + b_dst0 + i * 8 * 512, b_src0 + nx * bKstep + (long)i * 8 * Ntot);
        }
        asm volatile("cp.async.commit_group;" ::: "memory");

        rd += STAGE_BYTES; if (rd == hiS) rd = sb;
        wr += STAGE_BYTES; if (wr == hiS) wr = sb;
    }

    // epilogue
#pragma unroll
    for (int mi = 0; mi < 4; ++mi) {
        int row = bm * 128 + wm * 64 + mi * 16 + (lane >> 2);
#pragma unroll
        for (int ni = 0; ni < 8; ++ni) {
            int col = bn * 256 + wn * 64 + ni * 8 + (lane & 3) * 2;
            float bv0 = bias[col], bv1 = bias[col + 1];
            float v00 = acc[mi][ni][0] + bv0;
            float v01 = acc[mi][ni][1] + bv1;
            float v10 = acc[mi][ni][2] + bv0;
            float v11 = acc[mi][ni][3] + bv1;
            if (GELU) {
                v00 = gelu_exact(v00); v01 = gelu_exact(v01);
                v10 = gelu_exact(v10); v11 = gelu_exact(v11);
            }
            if (HALF_OUT) {
                __half* C = (__half*)Cv;
                *(__half2*)&C[(size_t)row * Ntot + col] = __floats2half2_rn(v00, v01);
                *(__half2*)&C[(size_t)(row + 8) * Ntot + col] = __floats2half2_rn(v10, v11);
            } else {
                float* C = (float*)Cv;
                *(float2*)&C[(size_t)row * Ntot + col] = make_float2(v00, v01);
                *(float2*)&C[(size_t)(row + 8) * Ntot + col] = make_float2(v10, v11);
            }
        }
    }
}

// ---------------- launch (triple-stream fork/join inside capture) -----------
extern "C" void kernel_launch(void* const* d_in, const int* in_sizes, int n_in,
                              void* d_out, int out_size) {
    const float* x   = (const float*)d_in[0];
    const float* sw1 = (const float*)d_in[1];
    const float* sb1 = (const float*)d_in[2];
    const float* sw2 = (const float*)d_in[3];
    const float* sb2 = (const float*)d_in[4];
    const float* rw  = (const float*)d_in[5];
    const float* rb  = (const float*)d_in[6];
    const float* ew1 = (const float*)d_in[7];
    const float* eb1 = (const float*)d_in[8];
    const float* ew2 = (const float*)d_in[9];
    const float* eb2 = (const float*)d_in[10];
    float* out = (float*)d_out;

    __half *xh, *w1h, *w2h, *ew1h, *ew2h, *Hsh, *Heh;
    float* Ye;
    cudaGetSymbolAddress((void**)&xh, g_xh);
    cudaGetSymbolAddress((void**)&w1h, g_w1h);
    cudaGetSymbolAddress((void**)&w2h, g_w2h);
    cudaGetSymbolAddress((void**)&ew1h, g_ew1h);
    cudaGetSymbolAddress((void**)&ew2h, g_ew2h);
    cudaGetSymbolAddress((void**)&Hsh, g_Hsh);
    cudaGetSymbolAddress((void**)&Heh, g_Heh);
    cudaGetSymbolAddress((void**)&Ye, g_Ye);

    static cudaStream_t s2 = 0, s3 = 0;
    static cudaEvent_t evFork = 0, evXh = 0, evExp = 0, evEw1 = 0, evEw2 = 0;
    if (!s2) {
        cudaStreamCreateWithFlags(&s2, cudaStreamNonBlocking);
        cudaStreamCreateWithFlags(&s3, cudaStreamNonBlocking);
        cudaEventCreateWithFlags(&evFork, cudaEventDisableTiming);
        cudaEventCreateWithFlags(&evXh, cudaEventDisableTiming);
        cudaEventCreateWithFlags(&evExp, cudaEventDisableTiming);
        cudaEventCreateWithFlags(&evEw1, cudaEventDisableTiming);
        cudaEventCreateWithFlags(&evEw2, cudaEventDisableTiming);

        cudaFuncSetAttribute(gemm_h<true, false, false, true>,
                             cudaFuncAttributeMaxDynamicSharedMemorySize, SMEM_TOTAL);
        cudaFuncSetAttribute(gemm_h<true, true, true, true>,
                             cudaFuncAttributeMaxDynamicSharedMemorySize, SMEM_TOTAL);
        cudaFuncSetAttribute(gemm_h<false, false, false, false>,
                             cudaFuncAttributeMaxDynamicSharedMemorySize, SMEM_TOTAL);
        cudaFuncSetAttribute(gemm_h<false, false, true, false>,
                             cudaFuncAttributeMaxDynamicSharedMemorySize, SMEM_TOTAL);
    }

    // ---- fork s2 and s3 off the capture-origin stream ----------------------
    cudaEventRecord(evFork, 0);
    cudaStreamWaitEvent(s2, evFork, 0);
    cudaStreamWaitEvent(s3, evFork, 0);

    // ---- s0: activation + shared-weight conversions, shared FFN chain ------
    f2h_kernel<<<(T_TOK * D_MODEL / 4) / 256, 256>>>(x, (__half2*)xh);
    cudaEventRecord(evXh, 0);
    f2h_kernel<<<(D_MODEL * D_FF / 4) / 256, 256>>>(sw1, (__half2*)w1h);

    // ---- s2: routing chain -------------------------------------------------
    init_kernel<<<1, 32, 0, s2>>>();
    router_kernel<<<T_TOK / 32, 256, 0, s2>>>(x, rw, rb);
    scan_kernel<<<1, 256, 0, s2>>>();
    gather_kernel<<<T_TOK / 256, 256, 0, s2>>>();

    // ---- s3: expert weight conversions (parallel with routing) -------------
    f2h_kernel<<<(N_EXP * D_MODEL * D_FF / 4) / 256, 256, 0, s3>>>(ew1, (__half2*)ew1h);
    cudaEventRecord(evEw1, s3);
    f2h_kernel<<<(N_EXP * D_FF * D_MODEL / 4) / 256, 256, 0, s3>>>(ew2, (__half2*)ew2h);
    cudaEventRecord(evEw2, s3);

    // ---- s0: shared FFN layer 1 --------------------------------------------
    gemm_h<true, false, false, true>
        <<<dim3(T_TOK / 128, D_FF / 256), 256, SMEM_TOTAL>>>(
            xh, w1h, sb1, Hsh, D_FF, D_MODEL, 0, 0);
    f2h_kernel<<<(D_FF * D_MODEL / 4) / 256, 256>>>(sw2, (__half2*)w2h);

    // ---- s2: expert FFN chain (GEMM1 needs xh+ew1; GEMM2 needs ew2) --------
    cudaStreamWaitEvent(s2, evXh, 0);
    cudaStreamWaitEvent(s2, evEw1, 0);
    gemm_h<true, true, true, true>
        <<<dim3(MAX_BLOCKS, D_FF / 256), 256, SMEM_TOTAL, s2>>>(
            xh, ew1h, eb1, Heh, D_FF, D_MODEL, (long)D_MODEL * D_FF, D_FF);
    cudaStreamWaitEvent(s2, evEw2, 0);
    gemm_h<false, false, true, false>
        <<<dim3(MAX_BLOCKS, D_MODEL / 256), 256, SMEM_TOTAL, s2>>>(
            Heh, ew2h, eb2, Ye, D_MODEL, D_FF, (long)D_FF * D_MODEL, D_MODEL);
    cudaEventRecord(evExp, s2);

    // ---- s0: shared FFN layer 2 -> out, then join + combine ----------------
    gemm_h<false, false, false, false>
        <<<dim3(T_TOK / 128, D_MODEL / 256), 256, SMEM_TOTAL>>>(
            Hsh, w2h, sb2, out, D_MODEL, D_FF, 0, 0);
    cudaStreamWaitEvent(0, evExp, 0);
    combine_kernel<<<T_TOK, 256>>>(out, Ye);
}

// round 16
// speedup vs baseline: 1.0761x; 1.0761x over previous
#include <cuda_runtime.h>
#include <cuda_fp16.h>
#include <math.h>
#include <stdint.h>

// ---------------------------------------------------------------------------
// SharedSpecialistMoEFFN — GB300 (sm_103, legacy tensor path), Round 15
// R13 frozen (GEMM BK=64/3-stage/occ2 + triple-stream schedule, 1128.5us)
// + router v2b: 2 tokens/warp, 512 blocks (occ x2 vs v2, 2x rw reuse).
// ---------------------------------------------------------------------------

#define D_MODEL 1024
#define D_FF    4096
#define N_EXP   8
#define T_TOK   8192
#define MAX_BLOCKS 136
#define MAX_SLOTS  (MAX_BLOCKS * 128)

#define STAGES      3
#define A_ROW       144                 // 128B data + 16B pad
#define A_STAGE_SZ  (128 * A_ROW)       // 18432
#define B_STAGE_SZ  (64 * 256)          // 16384
#define STAGE_BYTES (A_STAGE_SZ + B_STAGE_SZ)   // 34816
#define SMEM_TOTAL  (STAGES * STAGE_BYTES)      // 104448

// ---------------- scratch (device globals; zero runtime allocation) --------
__device__ __half g_xh[(size_t)T_TOK * D_MODEL];
__device__ __half g_w1h[(size_t)D_MODEL * D_FF];
__device__ __half g_w2h[(size_t)D_FF * D_MODEL];
__device__ __half g_ew1h[(size_t)N_EXP * D_MODEL * D_FF];
__device__ __half g_ew2h[(size_t)N_EXP * D_FF * D_MODEL];
__device__ __half g_Hsh[(size_t)T_TOK * D_FF];
__device__ __half g_Heh[(size_t)MAX_SLOTS * D_FF];
__device__ float  g_Ye[(size_t)MAX_SLOTS * D_MODEL];
__device__ int    g_perm[MAX_SLOTS];
__device__ int    g_topidx[T_TOK * 2];
__device__ float  g_topw[T_TOK * 2];
__device__ int    g_slot[T_TOK * 2];
__device__ int    g_counts[N_EXP];
__device__ int    g_cursor[N_EXP];
__device__ int    g_offsets[N_EXP];
__device__ int    g_blk_expert[MAX_BLOCKS];
__device__ int    g_nblocks;

// ---------------- helpers ---------------------------------------------------
__device__ __forceinline__ float gelu_exact(float v) {
    return 0.5f * v * (1.0f + erff(v * 0.70710678118654752f));
}
__device__ __forceinline__ uint32_t s2u(const void* p) {
    uint32_t a;
    asm("{ .reg .u64 t; cvta.to.shared.u64 t, %1; cvt.u32.u64 %0, t; }" : "=r"(a) : "l"(p));
    return a;
}
__device__ __forceinline__ void cp16(uint32_t dst, const void* src) {
    asm volatile("cp.async.cg.shared.global [%0], [%1], 16;" :: "r"(dst), "l"(src));
}
__device__ __forceinline__ void cp16s(uint32_t dst, const void* src, int sz) {
    asm volatile("cp.async.cg.shared.global [%0], [%1], 16, %2;"
                 :: "r"(dst), "l"(src), "r"(sz));
}
__device__ __forceinline__ void ldm_x4(uint32_t (&r)[4], uint32_t addr) {
    asm volatile("ldmatrix.sync.aligned.m8n8.x4.shared.b16 {%0,%1,%2,%3}, [%4];"
                 : "=r"(r[0]), "=r"(r[1]), "=r"(r[2]), "=r"(r[3]) : "r"(addr));
}
__device__ __forceinline__ void ldm_x4t(uint32_t* r, uint32_t addr) {
    asm volatile("ldmatrix.sync.aligned.m8n8.x4.trans.shared.b16 {%0,%1,%2,%3}, [%4];"
                 : "=r"(r[0]), "=r"(r[1]), "=r"(r[2]), "=r"(r[3]) : "r"(addr));
}
__device__ __forceinline__ void mma_f16(float c[4], const uint32_t a[4],
                                        uint32_t b0, uint32_t b1) {
    asm volatile(
        "mma.sync.aligned.m16n8k16.row.col.f32.f16.f16.f32 "
        "{%0,%1,%2,%3}, {%4,%5,%6,%7}, {%8,%9}, {%0,%1,%2,%3};\n"
        : "+f"(c[0]), "+f"(c[1]), "+f"(c[2]), "+f"(c[3])
        : "r"(a[0]), "r"(a[1]), "r"(a[2]), "r"(a[3]), "r"(b0), "r"(b1));
}

// ---------------- prep: fp32 -> fp16 ----------------------------------------
__global__ void f2h_kernel(const float* __restrict__ in, __half2* __restrict__ out) {
    size_t i = (size_t)blockIdx.x * blockDim.x + threadIdx.x;
    float4 v = ((const float4*)in)[i];
    out[i * 2 + 0] = __floats2half2_rn(v.x, v.y);
    out[i * 2 + 1] = __floats2half2_rn(v.z, v.w);
}

// ---------------- routing helpers -------------------------------------------
__global__ void init_kernel() {
    int i = threadIdx.x;
    if (i < N_EXP) { g_counts[i] = 0; g_cursor[i] = 0; }
}

// Router v2b: 2 tokens per warp, 512 blocks.
__global__ void router_kernel(const float* __restrict__ x,
                              const float* __restrict__ rw,
                              const float* __restrict__ rb) {
    int warp = threadIdx.x >> 5, lane = threadIdx.x & 31;
    int t0 = (blockIdx.x * 8 + warp) * 2;
    const float* xr = x + (size_t)t0 * D_MODEL;
    float acc[2][8];
#pragma unroll
    for (int tt = 0; tt < 2; ++tt)
#pragma unroll
        for (int e = 0; e < 8; ++e) acc[tt][e] = 0.f;
    for (int i = lane; i < D_MODEL; i += 32) {
        const float4* r = (const float4*)(rw + (size_t)i * 8);
        float4 rA = r[0], rB = r[1];
#pragma unroll
        for (int tt = 0; tt < 2; ++tt) {
            float xv = xr[(size_t)tt * D_MODEL + i];
            acc[tt][0] += xv * rA.x; acc[tt][1] += xv * rA.y;
            acc[tt][2] += xv * rA.z; acc[tt][3] += xv * rA.w;
            acc[tt][4] += xv * rB.x; acc[tt][5] += xv * rB.y;
            acc[tt][6] += xv * rB.z; acc[tt][7] += xv * rB.w;
        }
    }
#pragma unroll
    for (int off = 16; off; off >>= 1)
#pragma unroll
        for (int tt = 0; tt < 2; ++tt)
#pragma unroll
            for (int e = 0; e < 8; ++e)
                acc[tt][e] += __shfl_xor_sync(0xffffffffu, acc[tt][e], off);
    if (lane == 0) {
#pragma unroll
        for (int tt = 0; tt < 2; ++tt) {
            int t = t0 + tt;
            float l[8], m = -1e30f;
#pragma unroll
            for (int e = 0; e < 8; ++e) { l[e] = acc[tt][e] + rb[e]; m = fmaxf(m, l[e]); }
            float p[8], Z = 0.f;
#pragma unroll
            for (int e = 0; e < 8; ++e) { p[e] = expf(l[e] - m); Z += p[e]; }
#pragma unroll
            for (int e = 0; e < 8; ++e) p[e] /= Z;
            int i0 = 0;
#pragma unroll
            for (int e = 1; e < 8; ++e) if (p[e] > p[i0]) i0 = e;
            int i1 = -1;
            for (int e = 0; e < 8; ++e) if (e != i0 && (i1 < 0 || p[e] > p[i1])) i1 = e;
            float s = p[i0] + p[i1] + 1e-9f;
            g_topidx[t * 2 + 0] = i0;
            g_topidx[t * 2 + 1] = i1;
            g_topw[t * 2 + 0] = p[i0] / s;
            g_topw[t * 2 + 1] = p[i1] / s;
            atomicAdd(&g_counts[i0], 1);
            atomicAdd(&g_counts[i1], 1);
        }
    }
}

// scan + pad-fill
__global__ void scan_kernel() {
    __shared__ int offs[N_EXP], cnts[N_EXP], ends[N_EXP];
    if (threadIdx.x == 0) {
        int tb = 0;
        for (int e = 0; e < N_EXP; ++e) {
            int cnt = g_counts[e];
            offs[e] = tb * 128;
            cnts[e] = cnt;
            int nb = (cnt + 127) >> 7;
            for (int b = 0; b < nb; ++b) g_blk_expert[tb + b] = e;
            tb += nb;
            ends[e] = tb * 128;
        }
        g_nblocks = tb;
        for (int e = 0; e < N_EXP; ++e) g_offsets[e] = offs[e];
    }
    __syncthreads();
#pragma unroll
    for (int e = 0; e < N_EXP; ++e) {
        int start = offs[e] + cnts[e], end = ends[e];
        for (int i = start + threadIdx.x; i < end; i += blockDim.x)
            g_perm[i] = -1;
    }
}

__global__ void gather_kernel() {
    int t = blockIdx.x * blockDim.x + threadIdx.x;
    if (t >= T_TOK) return;
#pragma unroll
    for (int k = 0; k < 2; ++k) {
        int e = g_topidx[t * 2 + k];
        int pos = atomicAdd(&g_cursor[e], 1);
        int slot = g_offsets[e] + pos;
        g_perm[slot] = t;
        g_slot[t * 2 + k] = slot;
    }
}

__global__ void combine_kernel(float* __restrict__ out, const float* __restrict__ Ye) {
    int t = blockIdx.x;
    int col = threadIdx.x * 4;
    int s0 = g_slot[t * 2 + 0], s1 = g_slot[t * 2 + 1];
    float w0 = g_topw[t * 2 + 0], w1 = g_topw[t * 2 + 1];
    float4 o = *(const float4*)(out + (size_t)t * D_MODEL + col);
    float4 y0 = *(const float4*)(Ye + (size_t)s0 * D_MODEL + col);
    float4 y1 = *(const float4*)(Ye + (size_t)s1 * D_MODEL + col);
    o.x += w0 * y0.x + w1 * y1.x;
    o.y += w0 * y0.y + w1 * y1.y;
    o.z += w0 * y0.z + w1 * y1.z;
    o.w += w0 * y0.w + w1 * y1.w;
    *(float4*)(out + (size_t)t * D_MODEL + col) = o;
}

// ---------------- fp16 GEMM, BK=64, 3 stages (R13 frozen) --------------------
template <bool GELU, bool PERM, bool EXPERT, bool HALF_OUT>
__global__ __launch_bounds__(256, 2)
void gemm_h(const __half* __restrict__ A, const __half* __restrict__ Bw,
            const float* __restrict__ bias, void* __restrict__ Cv,
            int Ntot, int K, long wstride, long bstride) {
    int bm = blockIdx.x, bn = blockIdx.y;
    if (EXPERT) {
        if (bm >= g_nblocks) return;
        int e = g_blk_expert[bm];
        Bw += (long)e * wstride;
        bias += (long)e * bstride;
    }
    extern __shared__ char smem[];
    const uint32_t sb = s2u(smem);
    const int tid = threadIdx.x, lane = tid & 31, w = tid >> 5;
    const int wm = w & 1, wn = w >> 1;

    const __half* a_src[4]; uint32_t a_dst[4]; int a_sz[4];
#pragma unroll
    for (int i = 0; i < 4; ++i) {
        int c = tid + 256 * i, r = c >> 3, f = c & 7;
        a_dst[i] = (uint32_t)(r * A_ROW + f * 16);
        long row = PERM ? (long)g_perm[bm * 128 + r] : (long)bm * 128 + r;
        if (row >= 0) { a_src[i] = A + row * (long)K + f * 8; a_sz[i] = 16; }
        else          { a_src[i] = A;                          a_sz[i] = 0;  }
    }
    const __half* b_src[4]; uint32_t b_dst[4];
#pragma unroll
    for (int i = 0; i < 4; ++i) {
        int c = tid + 256 * i, k = c >> 4, j = c & 15;
        b_dst[i] = (uint32_t)(A_STAGE_SZ + k * 256 + (j ^ (k & 7)) * 16);
        b_src[i] = Bw + (long)k * Ntot + (long)bn * 128 + j * 8;
    }
    const long bKstep = (long)64 * Ntot;

    float acc[4][4][4];
#pragma unroll
    for (int i = 0; i < 4; ++i)
#pragma unroll
        for (int j = 0; j < 4; ++j)
#pragma unroll
            for (int q = 0; q < 4; ++q) acc[i][j][q] = 0.f;

    const int KT = K >> 6;

#pragma unroll
    for (int p = 0; p < STAGES - 1; ++p) {
        uint32_t st = sb + p * STAGE_BYTES;
#pragma unroll
        for (int i = 0; i < 4; ++i) cp16s(st + a_dst[i], a_src[i] + (long)p * 64, a_sz[i]);
#pragma unroll
        for (int i = 0; i < 4; ++i) cp16(st + b_dst[i], b_src[i] + (long)p * bKstep);
        asm volatile("cp.async.commit_group;" ::: "memory");
    }

    const uint32_t aBase = (uint32_t)((wm * 64 + (lane & 15)) * A_ROW + (lane >> 4) * 16);
    const uint32_t bBase = (uint32_t)(A_STAGE_SZ + (((lane >> 3) & 1) * 8 + (lane & 7)) * 256);
    const uint32_t bCh0 = (uint32_t)(((wn * 4 + 0 + (lane >> 4)) ^ (lane & 7)) * 16);
    const uint32_t bCh1 = (uint32_t)(((wn * 4 + 2 + (lane >> 4)) ^ (lane & 7)) * 16);

    uint32_t rd = sb;
    uint32_t wr = sb + 2 * STAGE_BYTES;
    const uint32_t hiS = sb + 3 * STAGE_BYTES;

    for (int kt = 0; kt < KT; ++kt) {
        asm volatile("cp.async.wait_group %0;" :: "n"(STAGES - 2) : "memory");
        __syncthreads();

        uint32_t bf[2][8];
        ldm_x4t(&bf[0][0], rd + bBase + bCh0);
        ldm_x4t(&bf[0][4], rd + bBase + bCh1);
#pragma unroll
        for (int kk = 0; kk < 4; ++kk) {
            const int cur = kk & 1;
            if (kk < 3) {
                ldm_x4t(&bf[cur ^ 1][0], rd + bBase + (kk + 1) * 16 * 256 + bCh0);
                ldm_x4t(&bf[cur ^ 1][4], rd + bBase + (kk + 1) * 16 * 256 + bCh1);
            }
            uint32_t af[4][4];
#pragma unroll
            for (int mi = 0; mi < 4; ++mi)
                ldm_x4(af[mi], rd + aBase + mi * 16 * A_ROW + kk * 32);
#pragma unroll
            for (int mi = 0; mi < 4; ++mi) {
                mma_f16(acc[mi][0], af[mi], bf[cur][0], bf[cur][1]);
                mma_f16(acc[mi][1], af[mi], bf[cur][2], bf[cur][3]);
                mma_f16(acc[mi][2], af[mi], bf[cur][4], bf[cur][5]);
                mma_f16(acc[mi][3], af[mi], bf[cur][6], bf[cur][7]);
            }
        }

        if (kt + STAGES - 1 < KT) {
            const long nx = kt + STAGES - 1;
#pragma unroll
            for (int i = 0; i < 4; ++i)
                cp16s(wr + a_dst[i], a_src[i] + nx * 64, a_sz[i]);
#pragma unroll
            for (int i = 0; i < 4; ++i)
                cp16(wr + b_dst[i], b_src[i] + nx * bKstep);
        }
        asm volatile("cp.async.commit_group;" ::: "memory");

        rd += STAGE_BYTES; if (rd == hiS) rd = sb;
        wr += STAGE_BYTES; if (wr == hiS) wr = sb;
    }

#pragma unroll
    for (int mi = 0; mi < 4; ++mi) {
        int row = bm * 128 + wm * 64 + mi * 16 + (lane >> 2);
#pragma unroll
        for (int ni = 0; ni < 4; ++ni) {
            int col = bn * 128 + wn * 32 + ni * 8 + (lane & 3) * 2;
            float bv0 = bias[col], bv1 = bias[col + 1];
            float v00 = acc[mi][ni][0] + bv0;
            float v01 = acc[mi][ni][1] + bv1;
            float v10 = acc[mi][ni][2] + bv0;
            float v11 = acc[mi][ni][3] + bv1;
            if (GELU) {
                v00 = gelu_exact(v00); v01 = gelu_exact(v01);
                v10 = gelu_exact(v10); v11 = gelu_exact(v11);
            }
            if (HALF_OUT) {
                __half* C = (__half*)Cv;
                *(__half2*)&C[(size_t)row * Ntot + col] = __floats2half2_rn(v00, v01);
                *(__half2*)&C[(size_t)(row + 8) * Ntot + col] = __floats2half2_rn(v10, v11);
            } else {
                float* C = (float*)Cv;
                *(float2*)&C[(size_t)row * Ntot + col] = make_float2(v00, v01);
                *(float2*)&C[(size_t)(row + 8) * Ntot + col] = make_float2(v10, v11);
            }
        }
    }
}

// ---------------- launch (triple-stream fork/join inside capture) -----------
extern "C" void kernel_launch(void* const* d_in, const int* in_sizes, int n_in,
                              void* d_out, int out_size) {
    const float* x   = (const float*)d_in[0];
    const float* sw1 = (const float*)d_in[1];
    const float* sb1 = (const float*)d_in[2];
    const float* sw2 = (const float*)d_in[3];
    const float* sb2 = (const float*)d_in[4];
    const float* rw  = (const float*)d_in[5];
    const float* rb  = (const float*)d_in[6];
    const float* ew1 = (const float*)d_in[7];
    const float* eb1 = (const float*)d_in[8];
    const float* ew2 = (const float*)d_in[9];
    const float* eb2 = (const float*)d_in[10];
    float* out = (float*)d_out;

    __half *xh, *w1h, *w2h, *ew1h, *ew2h, *Hsh, *Heh;
    float* Ye;
    cudaGetSymbolAddress((void**)&xh, g_xh);
    cudaGetSymbolAddress((void**)&w1h, g_w1h);
    cudaGetSymbolAddress((void**)&w2h, g_w2h);
    cudaGetSymbolAddress((void**)&ew1h, g_ew1h);
    cudaGetSymbolAddress((void**)&ew2h, g_ew2h);
    cudaGetSymbolAddress((void**)&Hsh, g_Hsh);
    cudaGetSymbolAddress((void**)&Heh, g_Heh);
    cudaGetSymbolAddress((void**)&Ye, g_Ye);

    static cudaStream_t s2 = 0, s3 = 0;
    static cudaEvent_t evFork = 0, evXh = 0, evExp = 0, evEw1 = 0, evEw2 = 0;
    if (!s2) {
        cudaStreamCreateWithFlags(&s2, cudaStreamNonBlocking);
        cudaStreamCreateWithFlags(&s3, cudaStreamNonBlocking);
        cudaEventCreateWithFlags(&evFork, cudaEventDisableTiming);
        cudaEventCreateWithFlags(&evXh, cudaEventDisableTiming);
        cudaEventCreateWithFlags(&evExp, cudaEventDisableTiming);
        cudaEventCreateWithFlags(&evEw1, cudaEventDisableTiming);
        cudaEventCreateWithFlags(&evEw2, cudaEventDisableTiming);

        cudaFuncSetAttribute(gemm_h<true, false, false, true>,
                             cudaFuncAttributeMaxDynamicSharedMemorySize, SMEM_TOTAL);
        cudaFuncSetAttribute(gemm_h<true, true, true, true>,
                             cudaFuncAttributeMaxDynamicSharedMemorySize, SMEM_TOTAL);
        cudaFuncSetAttribute(gemm_h<false, false, false, false>,
                             cudaFuncAttributeMaxDynamicSharedMemorySize, SMEM_TOTAL);
        cudaFuncSetAttribute(gemm_h<false, false, true, false>,
                             cudaFuncAttributeMaxDynamicSharedMemorySize, SMEM_TOTAL);
    }

    // ---- fork s2 and s3 off the capture-origin stream ----------------------
    cudaEventRecord(evFork, 0);
    cudaStreamWaitEvent(s2, evFork, 0);
    cudaStreamWaitEvent(s3, evFork, 0);

    // ---- s0: activation + shared-weight conversions, shared FFN chain ------
    f2h_kernel<<<(T_TOK * D_MODEL / 4) / 256, 256>>>(x, (__half2*)xh);
    cudaEventRecord(evXh, 0);
    f2h_kernel<<<(D_MODEL * D_FF / 4) / 256, 256>>>(sw1, (__half2*)w1h);

    // ---- s2: routing chain (router v2b: 2 tok/warp, 512 blocks) ------------
    init_kernel<<<1, 32, 0, s2>>>();
    router_kernel<<<T_TOK / 16, 256, 0, s2>>>(x, rw, rb);
    scan_kernel<<<1, 256, 0, s2>>>();
    gather_kernel<<<T_TOK / 256, 256, 0, s2>>>();

    // ---- s3: expert weight conversions (parallel with routing) -------------
    f2h_kernel<<<(N_EXP * D_MODEL * D_FF / 4) / 256, 256, 0, s3>>>(ew1, (__half2*)ew1h);
    cudaEventRecord(evEw1, s3);
    f2h_kernel<<<(N_EXP * D_FF * D_MODEL / 4) / 256, 256, 0, s3>>>(ew2, (__half2*)ew2h);
    cudaEventRecord(evEw2, s3);

    // ---- s0: shared FFN layer 1 --------------------------------------------
    gemm_h<true, false, false, true>
        <<<dim3(T_TOK / 128, D_FF / 128), 256, SMEM_TOTAL>>>(
            xh, w1h, sb1, Hsh, D_FF, D_MODEL, 0, 0);
    f2h_kernel<<<(D_FF * D_MODEL / 4) / 256, 256>>>(sw2, (__half2*)w2h);

    // ---- s2: expert FFN chain (GEMM1 needs xh+ew1; GEMM2 needs ew2) --------
    cudaStreamWaitEvent(s2, evXh, 0);
    cudaStreamWaitEvent(s2, evEw1, 0);
    gemm_h<true, true, true, true>
        <<<dim3(MAX_BLOCKS, D_FF / 128), 256, SMEM_TOTAL, s2>>>(
            xh, ew1h, eb1, Heh, D_FF, D_MODEL, (long)D_MODEL * D_FF, D_FF);
    cudaStreamWaitEvent(s2, evEw2, 0);
    gemm_h<false, false, true, false>
        <<<dim3(MAX_BLOCKS, D_MODEL / 128), 256, SMEM_TOTAL, s2>>>(
            Heh, ew2h, eb2, Ye, D_MODEL, D_FF, (long)D_FF * D_MODEL, D_MODEL);
    cudaEventRecord(evExp, s2);

    // ---- s0: shared FFN layer 2 -> out, then join + combine ----------------
    gemm_h<false, false, false, false>
        <<<dim3(T_TOK / 128, D_MODEL / 128), 256, SMEM_TOTAL>>>(
            Hsh, w2h, sb2, out, D_MODEL, D_FF, 0, 0);
    cudaStreamWaitEvent(0, evExp, 0);
    combine_kernel<<<T_TOK, 256>>>(out, Ye);
}

// round 17
// speedup vs baseline: 1.0819x; 1.0053x over previous
#include <cuda_runtime.h>
#include <cuda_fp16.h>
#include <math.h>
#include <stdint.h>

// ---------------------------------------------------------------------------
// SharedSpecialistMoEFFN — GB300 (sm_103, legacy tensor path), Round 16
// R13 frozen GEMM/schedule; f2h(sw2) moved off the s0 serial chain onto s3
// (overlaps shared GEMM1), shared GEMM2 gated by evW2.
// ---------------------------------------------------------------------------

#define D_MODEL 1024
#define D_FF    4096
#define N_EXP   8
#define T_TOK   8192
#define MAX_BLOCKS 136
#define MAX_SLOTS  (MAX_BLOCKS * 128)

#define STAGES      3
#define A_ROW       144                 // 128B data + 16B pad
#define A_STAGE_SZ  (128 * A_ROW)       // 18432
#define B_STAGE_SZ  (64 * 256)          // 16384
#define STAGE_BYTES (A_STAGE_SZ + B_STAGE_SZ)   // 34816
#define SMEM_TOTAL  (STAGES * STAGE_BYTES)      // 104448

// ---------------- scratch (device globals; zero runtime allocation) --------
__device__ __half g_xh[(size_t)T_TOK * D_MODEL];
__device__ __half g_w1h[(size_t)D_MODEL * D_FF];
__device__ __half g_w2h[(size_t)D_FF * D_MODEL];
__device__ __half g_ew1h[(size_t)N_EXP * D_MODEL * D_FF];
__device__ __half g_ew2h[(size_t)N_EXP * D_FF * D_MODEL];
__device__ __half g_Hsh[(size_t)T_TOK * D_FF];
__device__ __half g_Heh[(size_t)MAX_SLOTS * D_FF];
__device__ float  g_Ye[(size_t)MAX_SLOTS * D_MODEL];
__device__ int    g_perm[MAX_SLOTS];
__device__ int    g_topidx[T_TOK * 2];
__device__ float  g_topw[T_TOK * 2];
__device__ int    g_slot[T_TOK * 2];
__device__ int    g_counts[N_EXP];
__device__ int    g_cursor[N_EXP];
__device__ int    g_offsets[N_EXP];
__device__ int    g_blk_expert[MAX_BLOCKS];
__device__ int    g_nblocks;

// ---------------- helpers ---------------------------------------------------
__device__ __forceinline__ float gelu_exact(float v) {
    return 0.5f * v * (1.0f + erff(v * 0.70710678118654752f));
}
__device__ __forceinline__ uint32_t s2u(const void* p) {
    uint32_t a;
    asm("{ .reg .u64 t; cvta.to.shared.u64 t, %1; cvt.u32.u64 %0, t; }" : "=r"(a) : "l"(p));
    return a;
}
__device__ __forceinline__ void cp16(uint32_t dst, const void* src) {
    asm volatile("cp.async.cg.shared.global [%0], [%1], 16;" :: "r"(dst), "l"(src));
}
__device__ __forceinline__ void cp16s(uint32_t dst, const void* src, int sz) {
    asm volatile("cp.async.cg.shared.global [%0], [%1], 16, %2;"
                 :: "r"(dst), "l"(src), "r"(sz));
}
__device__ __forceinline__ void ldm_x4(uint32_t (&r)[4], uint32_t addr) {
    asm volatile("ldmatrix.sync.aligned.m8n8.x4.shared.b16 {%0,%1,%2,%3}, [%4];"
                 : "=r"(r[0]), "=r"(r[1]), "=r"(r[2]), "=r"(r[3]) : "r"(addr));
}
__device__ __forceinline__ void ldm_x4t(uint32_t* r, uint32_t addr) {
    asm volatile("ldmatrix.sync.aligned.m8n8.x4.trans.shared.b16 {%0,%1,%2,%3}, [%4];"
                 : "=r"(r[0]), "=r"(r[1]), "=r"(r[2]), "=r"(r[3]) : "r"(addr));
}
__device__ __forceinline__ void mma_f16(float c[4], const uint32_t a[4],
                                        uint32_t b0, uint32_t b1) {
    asm volatile(
        "mma.sync.aligned.m16n8k16.row.col.f32.f16.f16.f32 "
        "{%0,%1,%2,%3}, {%4,%5,%6,%7}, {%8,%9}, {%0,%1,%2,%3};\n"
        : "+f"(c[0]), "+f"(c[1]), "+f"(c[2]), "+f"(c[3])
        : "r"(a[0]), "r"(a[1]), "r"(a[2]), "r"(a[3]), "r"(b0), "r"(b1));
}

// ---------------- prep: fp32 -> fp16 ----------------------------------------
__global__ void f2h_kernel(const float* __restrict__ in, __half2* __restrict__ out) {
    size_t i = (size_t)blockIdx.x * blockDim.x + threadIdx.x;
    float4 v = ((const float4*)in)[i];
    out[i * 2 + 0] = __floats2half2_rn(v.x, v.y);
    out[i * 2 + 1] = __floats2half2_rn(v.z, v.w);
}

// ---------------- routing helpers -------------------------------------------
__global__ void init_kernel() {
    int i = threadIdx.x;
    if (i < N_EXP) { g_counts[i] = 0; g_cursor[i] = 0; }
}

// Router v2 (variant used in the 1128.5us best run): 4 tokens per warp.
__global__ void router_kernel(const float* __restrict__ x,
                              const float* __restrict__ rw,
                              const float* __restrict__ rb) {
    int warp = threadIdx.x >> 5, lane = threadIdx.x & 31;
    int t0 = (blockIdx.x * 8 + warp) * 4;
    const float* xr = x + (size_t)t0 * D_MODEL;
    float acc[4][8];
#pragma unroll
    for (int tt = 0; tt < 4; ++tt)
#pragma unroll
        for (int e = 0; e < 8; ++e) acc[tt][e] = 0.f;
    for (int i = lane; i < D_MODEL; i += 32) {
        const float4* r = (const float4*)(rw + (size_t)i * 8);
        float4 rA = r[0], rB = r[1];
#pragma unroll
        for (int tt = 0; tt < 4; ++tt) {
            float xv = xr[(size_t)tt * D_MODEL + i];
            acc[tt][0] += xv * rA.x; acc[tt][1] += xv * rA.y;
            acc[tt][2] += xv * rA.z; acc[tt][3] += xv * rA.w;
            acc[tt][4] += xv * rB.x; acc[tt][5] += xv * rB.y;
            acc[tt][6] += xv * rB.z; acc[tt][7] += xv * rB.w;
        }
    }
#pragma unroll
    for (int off = 16; off; off >>= 1)
#pragma unroll
        for (int tt = 0; tt < 4; ++tt)
#pragma unroll
            for (int e = 0; e < 8; ++e)
                acc[tt][e] += __shfl_xor_sync(0xffffffffu, acc[tt][e], off);
    if (lane == 0) {
#pragma unroll
        for (int tt = 0; tt < 4; ++tt) {
            int t = t0 + tt;
            float l[8], m = -1e30f;
#pragma unroll
            for (int e = 0; e < 8; ++e) { l[e] = acc[tt][e] + rb[e]; m = fmaxf(m, l[e]); }
            float p[8], Z = 0.f;
#pragma unroll
            for (int e = 0; e < 8; ++e) { p[e] = expf(l[e] - m); Z += p[e]; }
#pragma unroll
            for (int e = 0; e < 8; ++e) p[e] /= Z;
            int i0 = 0;
#pragma unroll
            for (int e = 1; e < 8; ++e) if (p[e] > p[i0]) i0 = e;
            int i1 = -1;
            for (int e = 0; e < 8; ++e) if (e != i0 && (i1 < 0 || p[e] > p[i1])) i1 = e;
            float s = p[i0] + p[i1] + 1e-9f;
            g_topidx[t * 2 + 0] = i0;
            g_topidx[t * 2 + 1] = i1;
            g_topw[t * 2 + 0] = p[i0] / s;
            g_topw[t * 2 + 1] = p[i1] / s;
            atomicAdd(&g_counts[i0], 1);
            atomicAdd(&g_counts[i1], 1);
        }
    }
}

// scan + pad-fill
__global__ void scan_kernel() {
    __shared__ int offs[N_EXP], cnts[N_EXP], ends[N_EXP];
    if (threadIdx.x == 0) {
        int tb = 0;
        for (int e = 0; e < N_EXP; ++e) {
            int cnt = g_counts[e];
            offs[e] = tb * 128;
            cnts[e] = cnt;
            int nb = (cnt + 127) >> 7;
            for (int b = 0; b < nb; ++b) g_blk_expert[tb + b] = e;
            tb += nb;
            ends[e] = tb * 128;
        }
        g_nblocks = tb;
        for (int e = 0; e < N_EXP; ++e) g_offsets[e] = offs[e];
    }
    __syncthreads();
#pragma unroll
    for (int e = 0; e < N_EXP; ++e) {
        int start = offs[e] + cnts[e], end = ends[e];
        for (int i = start + threadIdx.x; i < end; i += blockDim.x)
            g_perm[i] = -1;
    }
}

__global__ void gather_kernel() {
    int t = blockIdx.x * blockDim.x + threadIdx.x;
    if (t >= T_TOK) return;
#pragma unroll
    for (int k = 0; k < 2; ++k) {
        int e = g_topidx[t * 2 + k];
        int pos = atomicAdd(&g_cursor[e], 1);
        int slot = g_offsets[e] + pos;
        g_perm[slot] = t;
        g_slot[t * 2 + k] = slot;
    }
}

__global__ void combine_kernel(float* __restrict__ out, const float* __restrict__ Ye) {
    int t = blockIdx.x;
    int col = threadIdx.x * 4;
    int s0 = g_slot[t * 2 + 0], s1 = g_slot[t * 2 + 1];
    float w0 = g_topw[t * 2 + 0], w1 = g_topw[t * 2 + 1];
    float4 o = *(const float4*)(out + (size_t)t * D_MODEL + col);
    float4 y0 = *(const float4*)(Ye + (size_t)s0 * D_MODEL + col);
    float4 y1 = *(const float4*)(Ye + (size_t)s1 * D_MODEL + col);
    o.x += w0 * y0.x + w1 * y1.x;
    o.y += w0 * y0.y + w1 * y1.y;
    o.z += w0 * y0.z + w1 * y1.z;
    o.w += w0 * y0.w + w1 * y1.w;
    *(float4*)(out + (size_t)t * D_MODEL + col) = o;
}

// ---------------- fp16 GEMM, BK=64, 3 stages (frozen best) -------------------
template <bool GELU, bool PERM, bool EXPERT, bool HALF_OUT>
__global__ __launch_bounds__(256, 2)
void gemm_h(const __half* __restrict__ A, const __half* __restrict__ Bw,
            const float* __restrict__ bias, void* __restrict__ Cv,
            int Ntot, int K, long wstride, long bstride) {
    int bm = blockIdx.x, bn = blockIdx.y;
    if (EXPERT) {
        if (bm >= g_nblocks) return;
        int e = g_blk_expert[bm];
        Bw += (long)e * wstride;
        bias += (long)e * bstride;
    }
    extern __shared__ char smem[];
    const uint32_t sb = s2u(smem);
    const int tid = threadIdx.x, lane = tid & 31, w = tid >> 5;
    const int wm = w & 1, wn = w >> 1;

    const __half* a_src[4]; uint32_t a_dst[4]; int a_sz[4];
#pragma unroll
    for (int i = 0; i < 4; ++i) {
        int c = tid + 256 * i, r = c >> 3, f = c & 7;
        a_dst[i] = (uint32_t)(r * A_ROW + f * 16);
        long row = PERM ? (long)g_perm[bm * 128 + r] : (long)bm * 128 + r;
        if (row >= 0) { a_src[i] = A + row * (long)K + f * 8; a_sz[i] = 16; }
        else          { a_src[i] = A;                          a_sz[i] = 0;  }
    }
    const __half* b_src[4]; uint32_t b_dst[4];
#pragma unroll
    for (int i = 0; i < 4; ++i) {
        int c = tid + 256 * i, k = c >> 4, j = c & 15;
        b_dst[i] = (uint32_t)(A_STAGE_SZ + k * 256 + (j ^ (k & 7)) * 16);
        b_src[i] = Bw + (long)k * Ntot + (long)bn * 128 + j * 8;
    }
    const long bKstep = (long)64 * Ntot;

    float acc[4][4][4];
#pragma unroll
    for (int i = 0; i < 4; ++i)
#pragma unroll
        for (int j = 0; j < 4; ++j)
#pragma unroll
            for (int q = 0; q < 4; ++q) acc[i][j][q] = 0.f;

    const int KT = K >> 6;

#pragma unroll
    for (int p = 0; p < STAGES - 1; ++p) {
        uint32_t st = sb + p * STAGE_BYTES;
#pragma unroll
        for (int i = 0; i < 4; ++i) cp16s(st + a_dst[i], a_src[i] + (long)p * 64, a_sz[i]);
#pragma unroll
        for (int i = 0; i < 4; ++i) cp16(st + b_dst[i], b_src[i] + (long)p * bKstep);
        asm volatile("cp.async.commit_group;" ::: "memory");
    }

    const uint32_t aBase = (uint32_t)((wm * 64 + (lane & 15)) * A_ROW + (lane >> 4) * 16);
    const uint32_t bBase = (uint32_t)(A_STAGE_SZ + (((lane >> 3) & 1) * 8 + (lane & 7)) * 256);
    const uint32_t bCh0 = (uint32_t)(((wn * 4 + 0 + (lane >> 4)) ^ (lane & 7)) * 16);
    const uint32_t bCh1 = (uint32_t)(((wn * 4 + 2 + (lane >> 4)) ^ (lane & 7)) * 16);

    uint32_t rd = sb;
    uint32_t wr = sb + 2 * STAGE_BYTES;
    const uint32_t hiS = sb + 3 * STAGE_BYTES;

    for (int kt = 0; kt < KT; ++kt) {
        asm volatile("cp.async.wait_group %0;" :: "n"(STAGES - 2) : "memory");
        __syncthreads();

        uint32_t bf[2][8];
        ldm_x4t(&bf[0][0], rd + bBase + bCh0);
        ldm_x4t(&bf[0][4], rd + bBase + bCh1);
#pragma unroll
        for (int kk = 0; kk < 4; ++kk) {
            const int cur = kk & 1;
            if (kk < 3) {
                ldm_x4t(&bf[cur ^ 1][0], rd + bBase + (kk + 1) * 16 * 256 + bCh0);
                ldm_x4t(&bf[cur ^ 1][4], rd + bBase + (kk + 1) * 16 * 256 + bCh1);
            }
            uint32_t af[4][4];
#pragma unroll
            for (int mi = 0; mi < 4; ++mi)
                ldm_x4(af[mi], rd + aBase + mi * 16 * A_ROW + kk * 32);
#pragma unroll
            for (int mi = 0; mi < 4; ++mi) {
                mma_f16(acc[mi][0], af[mi], bf[cur][0], bf[cur][1]);
                mma_f16(acc[mi][1], af[mi], bf[cur][2], bf[cur][3]);
                mma_f16(acc[mi][2], af[mi], bf[cur][4], bf[cur][5]);
                mma_f16(acc[mi][3], af[mi], bf[cur][6], bf[cur][7]);
            }
        }

        if (kt + STAGES - 1 < KT) {
            const long nx = kt + STAGES - 1;
#pragma unroll
            for (int i = 0; i < 4; ++i)
                cp16s(wr + a_dst[i], a_src[i] + nx * 64, a_sz[i]);
#pragma unroll
            for (int i = 0; i < 4; ++i)
                cp16(wr + b_dst[i], b_src[i] + nx * bKstep);
        }
        asm volatile("cp.async.commit_group;" ::: "memory");

        rd += STAGE_BYTES; if (rd == hiS) rd = sb;
        wr += STAGE_BYTES; if (wr == hiS) wr = sb;
    }

#pragma unroll
    for (int mi = 0; mi < 4; ++mi) {
        int row = bm * 128 + wm * 64 + mi * 16 + (lane >> 2);
#pragma unroll
        for (int ni = 0; ni < 4; ++ni) {
            int col = bn * 128 + wn * 32 + ni * 8 + (lane & 3) * 2;
            float bv0 = bias[col], bv1 = bias[col + 1];
            float v00 = acc[mi][ni][0] + bv0;
            float v01 = acc[mi][ni][1] + bv1;
            float v10 = acc[mi][ni][2] + bv0;
            float v11 = acc[mi][ni][3] + bv1;
            if (GELU) {
                v00 = gelu_exact(v00); v01 = gelu_exact(v01);
                v10 = gelu_exact(v10); v11 = gelu_exact(v11);
            }
            if (HALF_OUT) {
                __half* C = (__half*)Cv;
                *(__half2*)&C[(size_t)row * Ntot + col] = __floats2half2_rn(v00, v01);
                *(__half2*)&C[(size_t)(row + 8) * Ntot + col] = __floats2half2_rn(v10, v11);
            } else {
                float* C = (float*)Cv;
                *(float2*)&C[(size_t)row * Ntot + col] = make_float2(v00, v01);
                *(float2*)&C[(size_t)(row + 8) * Ntot + col] = make_float2(v10, v11);
            }
        }
    }
}

// ---------------- launch (triple-stream fork/join inside capture) -----------
extern "C" void kernel_launch(void* const* d_in, const int* in_sizes, int n_in,
                              void* d_out, int out_size) {
    const float* x   = (const float*)d_in[0];
    const float* sw1 = (const float*)d_in[1];
    const float* sb1 = (const float*)d_in[2];
    const float* sw2 = (const float*)d_in[3];
    const float* sb2 = (const float*)d_in[4];
    const float* rw  = (const float*)d_in[5];
    const float* rb  = (const float*)d_in[6];
    const float* ew1 = (const float*)d_in[7];
    const float* eb1 = (const float*)d_in[8];
    const float* ew2 = (const float*)d_in[9];
    const float* eb2 = (const float*)d_in[10];
    float* out = (float*)d_out;

    __half *xh, *w1h, *w2h, *ew1h, *ew2h, *Hsh, *Heh;
    float* Ye;
    cudaGetSymbolAddress((void**)&xh, g_xh);
    cudaGetSymbolAddress((void**)&w1h, g_w1h);
    cudaGetSymbolAddress((void**)&w2h, g_w2h);
    cudaGetSymbolAddress((void**)&ew1h, g_ew1h);
    cudaGetSymbolAddress((void**)&ew2h, g_ew2h);
    cudaGetSymbolAddress((void**)&Hsh, g_Hsh);
    cudaGetSymbolAddress((void**)&Heh, g_Heh);
    cudaGetSymbolAddress((void**)&Ye, g_Ye);

    static cudaStream_t s2 = 0, s3 = 0;
    static cudaEvent_t evFork = 0, evXh = 0, evExp = 0, evEw1 = 0, evEw2 = 0, evW2 = 0;
    if (!s2) {
        cudaStreamCreateWithFlags(&s2, cudaStreamNonBlocking);
        cudaStreamCreateWithFlags(&s3, cudaStreamNonBlocking);
        cudaEventCreateWithFlags(&evFork, cudaEventDisableTiming);
        cudaEventCreateWithFlags(&evXh, cudaEventDisableTiming);
        cudaEventCreateWithFlags(&evExp, cudaEventDisableTiming);
        cudaEventCreateWithFlags(&evEw1, cudaEventDisableTiming);
        cudaEventCreateWithFlags(&evEw2, cudaEventDisableTiming);
        cudaEventCreateWithFlags(&evW2, cudaEventDisableTiming);

        cudaFuncSetAttribute(gemm_h<true, false, false, true>,
                             cudaFuncAttributeMaxDynamicSharedMemorySize, SMEM_TOTAL);
        cudaFuncSetAttribute(gemm_h<true, true, true, true>,
                             cudaFuncAttributeMaxDynamicSharedMemorySize, SMEM_TOTAL);
        cudaFuncSetAttribute(gemm_h<false, false, false, false>,
                             cudaFuncAttributeMaxDynamicSharedMemorySize, SMEM_TOTAL);
        cudaFuncSetAttribute(gemm_h<false, false, true, false>,
                             cudaFuncAttributeMaxDynamicSharedMemorySize, SMEM_TOTAL);
    }

    // ---- fork s2 and s3 off the capture-origin stream ----------------------
    cudaEventRecord(evFork, 0);
    cudaStreamWaitEvent(s2, evFork, 0);
    cudaStreamWaitEvent(s3, evFork, 0);

    // ---- s0: activation + w1 conversions, then shared FFN chain ------------
    f2h_kernel<<<(T_TOK * D_MODEL / 4) / 256, 256>>>(x, (__half2*)xh);
    cudaEventRecord(evXh, 0);
    f2h_kernel<<<(D_MODEL * D_FF / 4) / 256, 256>>>(sw1, (__half2*)w1h);

    // ---- s2: routing chain -------------------------------------------------
    init_kernel<<<1, 32, 0, s2>>>();
    router_kernel<<<T_TOK / 32, 256, 0, s2>>>(x, rw, rb);
    scan_kernel<<<1, 256, 0, s2>>>();
    gather_kernel<<<T_TOK / 256, 256, 0, s2>>>();

    // ---- s3: expert weight + sw2 conversions (all off the s0 chain) --------
    f2h_kernel<<<(N_EXP * D_MODEL * D_FF / 4) / 256, 256, 0, s3>>>(ew1, (__half2*)ew1h);
    cudaEventRecord(evEw1, s3);
    f2h_kernel<<<(D_FF * D_MODEL / 4) / 256, 256, 0, s3>>>(sw2, (__half2*)w2h);
    cudaEventRecord(evW2, s3);
    f2h_kernel<<<(N_EXP * D_FF * D_MODEL / 4) / 256, 256, 0, s3>>>(ew2, (__half2*)ew2h);
    cudaEventRecord(evEw2, s3);

    // ---- s0: shared FFN layer 1 --------------------------------------------
    gemm_h<true, false, false, true>
        <<<dim3(T_TOK / 128, D_FF / 128), 256, SMEM_TOTAL>>>(
            xh, w1h, sb1, Hsh, D_FF, D_MODEL, 0, 0);

    // ---- s2: expert FFN chain (GEMM1 needs xh+ew1; GEMM2 needs ew2) --------
    cudaStreamWaitEvent(s2, evXh, 0);
    cudaStreamWaitEvent(s2, evEw1, 0);
    gemm_h<true, true, true, true>
        <<<dim3(MAX_BLOCKS, D_FF / 128), 256, SMEM_TOTAL, s2>>>(
            xh, ew1h, eb1, Heh, D_FF, D_MODEL, (long)D_MODEL * D_FF, D_FF);
    cudaStreamWaitEvent(s2, evEw2, 0);
    gemm_h<false, false, true, false>
        <<<dim3(MAX_BLOCKS, D_MODEL / 128), 256, SMEM_TOTAL, s2>>>(
            Heh, ew2h, eb2, Ye, D_MODEL, D_FF, (long)D_FF * D_MODEL, D_MODEL);
    cudaEventRecord(evExp, s2);

    // ---- s0: shared FFN layer 2 -> out (waits w2h), then join + combine ----
    cudaStreamWaitEvent(0, evW2, 0);
    gemm_h<false, false, false, false>
        <<<dim3(T_TOK / 128, D_MODEL / 128), 256, SMEM_TOTAL>>>(
            Hsh, w2h, sb2, out, D_MODEL, D_FF, 0, 0);
    cudaStreamWaitEvent(0, evExp, 0);
    combine_kernel<<<T_TOK, 256>>>(out, Ye);
}